// round 12
// baseline (speedup 1.0000x reference)
#include <cuda_runtime.h>
#include <cuda_fp16.h>
#include <math.h>
#include <stdint.h>

#define BATCH 8
#define TT 4096
#define NMELS 26
#define CONV_K 5
#define CH 64
#define WF 32

__device__ float g_xc[BATCH * TT * CH];
__device__ float g_a [BATCH * TT * CH];
__device__ uint4 g_xch[262144]; // fp16 copy of g_xc (4MB)
__device__ uint4 g_w1h[65536];  // 32 chunks x 32KB fp16 swizzled [n256][k64]
__device__ uint4 g_swh[8192];   //  8 chunks x 16KB [n128][k64]
__device__ uint4 g_w2h[4096];   //  4 chunks x 16KB [n128][k64]

__device__ __forceinline__ uint32_t smem_u32(const void* p) {
    uint32_t a;
    asm("{ .reg .u64 t; cvta.to.shared.u64 t, %1; cvt.u32.u64 %0, t; }" : "=r"(a) : "l"(p));
    return a;
}
__device__ __forceinline__ uint32_t sw128(uint32_t o) { return o ^ ((o >> 3) & 0x70); }
__device__ __forceinline__ void ldsm4(uint32_t (&r)[4], uint32_t a) {
    asm volatile("ldmatrix.sync.aligned.m8n8.x4.shared.b16 {%0,%1,%2,%3}, [%4];"
                 : "=r"(r[0]), "=r"(r[1]), "=r"(r[2]), "=r"(r[3]) : "r"(a));
}
__device__ __forceinline__ void mma16816(float (&d)[4], const uint32_t (&a)[4],
                                         uint32_t b0, uint32_t b1) {
    asm volatile("mma.sync.aligned.m16n8k16.row.col.f32.f16.f16.f32 "
                 "{%0,%1,%2,%3}, {%4,%5,%6,%7}, {%8,%9}, {%0,%1,%2,%3};"
                 : "+f"(d[0]), "+f"(d[1]), "+f"(d[2]), "+f"(d[3])
                 : "r"(a[0]), "r"(a[1]), "r"(a[2]), "r"(a[3]), "r"(b0), "r"(b1));
}
__device__ __forceinline__ void cp16(uint32_t dst, const void* src) {
    asm volatile("cp.async.cg.shared.global [%0], [%1], 16;" :: "r"(dst), "l"(src));
}
#define CP_COMMIT() asm volatile("cp.async.commit_group;" ::: "memory")
#define CP_WAIT(n)  asm volatile("cp.async.wait_group %0;" :: "n"(n) : "memory")

// ---------------------------------------------------------------------------
// fused conv (blocks [0,256), 128 tokens each) + prep tiles (blocks [256,408))
// prep: coalesced 64k x 64n tile transpose -> fp16 swizzled chunk images.
// ---------------------------------------------------------------------------
__global__ __launch_bounds__(256, 4) void prep_conv_kernel(
    const float* __restrict__ x, const float* __restrict__ cw,
    const float* __restrict__ cb, const float* __restrict__ w1,
    const float* __restrict__ w2, const float* __restrict__ swp)
{
    __shared__ __align__(16) float sbuf[11816];
    const int tid = threadIdx.x;

    if (blockIdx.x >= 256) {   // ---- prep tile ----
        const int t = blockIdx.x - 256;
        const float* src; unsigned short* dstbase; int N, n0;
        if (t < 128) {
            int f = t >> 2; n0 = (t & 3) * 64;
            src = w1 + (size_t)f * 64 * 256; N = 256;
            dstbase = (unsigned short*)g_w1h + f * 16384;
        } else if (t < 144) {
            int u = t - 128, j = u >> 1; n0 = (u & 1) * 64;
            src = swp + (size_t)j * 64 * 128; N = 128;
            dstbase = (unsigned short*)g_swh + j * 8192;
        } else {
            int u = t - 144, c = u >> 1; n0 = (u & 1) * 64;
            src = w2 + (size_t)c * 64 * 128; N = 128;
            dstbase = (unsigned short*)g_w2h + c * 8192;
        }
        unsigned short* sh = (unsigned short*)sbuf;
        #pragma unroll
        for (int it = 0; it < 16; ++it) {
            int e = it * 256 + tid, kk = e >> 6, nn = e & 63;
            sh[kk * 64 + nn] = __half_as_ushort(__float2half_rn(src[kk * N + n0 + nn]));
        }
        __syncthreads();
        #pragma unroll
        for (int j2 = 0; j2 < 2; ++j2) {
            int G = tid + 256 * j2, n = G >> 3, grp = G & 7, kk0 = grp * 8;
            uint32_t u[4];
            #pragma unroll
            for (int q = 0; q < 4; ++q) {
                uint32_t lo = sh[(kk0 + 2 * q) * 64 + n];
                uint32_t hi = sh[(kk0 + 2 * q + 1) * 64 + n];
                u[q] = lo | (hi << 16);
            }
            uint32_t off = sw128((uint32_t)((n0 + n) * 128 + kk0 * 2));
            *(uint4*)((char*)dstbase + off) = make_uint4(u[0], u[1], u[2], u[3]);
        }
        return;
    }

    // ---- conv: 128 tokens per block ----
    float* xsh = sbuf;             // 132*26 = 3432
    float* wsh = sbuf + 3432;      // 8320
    float* bsh = sbuf + 11752;     // 64
    const int bb = blockIdx.x;
    const int b = bb >> 5, t0 = (bb & 31) << 7;
    for (int idx = tid; idx < 132 * NMELS; idx += 256) {
        int r = idx / NMELS, m = idx - r * NMELS, t = t0 - 4 + r;
        xsh[idx] = (t >= 0) ? x[(b * TT + t) * NMELS + m] : 0.f;
    }
    for (int idx = tid; idx < CONV_K * NMELS * CH; idx += 256) wsh[idx] = cw[idx];
    if (tid < CH) bsh[tid] = cb[tid];
    __syncthreads();
    const int c = tid & 63, tg = tid >> 6;
    unsigned short* xch = (unsigned short*)g_xch;
    for (int g = 0; g < 4; ++g) {
        float acc[8];
        #pragma unroll
        for (int i = 0; i < 8; ++i) acc[i] = bsh[c];
        #pragma unroll
        for (int k = 0; k < CONV_K; ++k)
            #pragma unroll
            for (int m = 0; m < NMELS; ++m) {
                float w = wsh[(k * NMELS + m) * CH + c];
                int base = (tg * 32 + g * 8 + k) * NMELS + m;
                #pragma unroll
                for (int i = 0; i < 8; ++i)
                    acc[i] = fmaf(xsh[base + i * NMELS], w, acc[i]);
            }
        #pragma unroll
        for (int i = 0; i < 8; ++i) {
            size_t idx = (size_t)(b * TT + t0 + tg * 32 + g * 8 + i) * CH + c;
            float v = fmaxf(acc[i], 0.f);
            g_xc[idx] = v;
            xch[idx] = __half_as_ushort(__float2half_rn(v));
        }
    }
}

// ---------------------------------------------------------------------------
__global__ __launch_bounds__(256) void se_kernel(
    const float* __restrict__ sew1, const float* __restrict__ seb1,
    const float* __restrict__ sew2, const float* __restrict__ seb2)
{
    extern __shared__ float sm2[];
    float* xsh = sm2; float* ssh = sm2 + 10176; float* w1s = sm2 + 18496;
    float* w2s = sm2 + 19520; float* b1s = sm2 + 20544; float* b2s = sm2 + 20560;
    const int b = blockIdx.x >> 5, t0 = (blockIdx.x & 31) << 7, tid = threadIdx.x;
    for (int idx = tid; idx < 159 * CH; idx += 256) {
        int r = idx >> 6, cc = idx & 63, t = t0 - 31 + r;
        xsh[idx] = (t >= 0) ? g_xc[(b * TT + t) * CH + cc] : 0.f;
    }
    for (int idx = tid; idx < 1024; idx += 256) { w1s[idx] = sew1[idx]; w2s[idx] = sew2[idx]; }
    if (tid < 16) b1s[tid] = seb1[tid];
    if (tid < CH) b2s[tid] = seb2[tid];
    __syncthreads();
    {
        const int c = tid & 63, tb = (tid >> 6) * 32;
        float s = 0.f;
        #pragma unroll
        for (int f = 0; f < WF; ++f) s += xsh[(tb + f) * CH + c];
        ssh[tb * 65 + c] = s * 0.03125f;
        for (int i = 1; i < 32; ++i) {
            s += xsh[(tb + i + 31) * CH + c] - xsh[(tb + i - 1) * CH + c];
            ssh[(tb + i) * 65 + c] = s * 0.03125f;
        }
    }
    __syncthreads();
    if (tid < 128) {
        float hid[16];
        #pragma unroll
        for (int j = 0; j < 16; ++j) hid[j] = b1s[j];
        for (int cc = 0; cc < CH; ++cc) {
            float sv = ssh[tid * 65 + cc];
            #pragma unroll
            for (int j = 0; j < 16; ++j) hid[j] = fmaf(sv, w1s[cc * 16 + j], hid[j]);
        }
        #pragma unroll
        for (int j = 0; j < 16; ++j) hid[j] = fmaxf(hid[j], 0.f);
        for (int cc = 0; cc < CH; ++cc) {
            float v = b2s[cc];
            #pragma unroll
            for (int j = 0; j < 16; ++j) v = fmaf(hid[j], w2s[j * CH + cc], v);
            g_a[(b * TT + t0 + tid) * CH + cc] = 1.f / (1.f + expf(-v));
        }
    }
}

// ---------------------------------------------------------------------------
// main kernel: unchanged from the 172.8us version (Round 11).
// ---------------------------------------------------------------------------
#define XSH_B 5120
#define AT_B  28160
#define BT_B  93696
#define SMEM_TOT 224768

__device__ __forceinline__ void build_A(uint32_t smb, int f, int slot, int tid,
                                        const uint32_t (&gv)[8])
{
    const int m = tid >> 2, kq = (tid & 3) << 4;
    uint32_t xaddr = smb + XSH_B + (uint32_t)(((m + f) * 72 + kq) * 2);
    uint32_t o = (uint32_t)(m * 128 + kq * 2);
    uint32_t abase = smb + AT_B + (uint32_t)slot * 16384u;
    uint32_t dst0 = abase + sw128(o);
    uint32_t dst1 = abase + sw128(o + 16);
    uint32_t xv[8], h[8];
    asm("ld.shared.v4.b32 {%0,%1,%2,%3}, [%4];"
        : "=r"(xv[0]), "=r"(xv[1]), "=r"(xv[2]), "=r"(xv[3]) : "r"(xaddr));
    asm("ld.shared.v4.b32 {%0,%1,%2,%3}, [%4];"
        : "=r"(xv[4]), "=r"(xv[5]), "=r"(xv[6]), "=r"(xv[7]) : "r"(xaddr + 16));
    #pragma unroll
    for (int i = 0; i < 8; ++i)
        asm("mul.rn.f16x2 %0, %1, %2;" : "=r"(h[i]) : "r"(xv[i]), "r"(gv[i]));
    asm volatile("st.shared.v4.b32 [%0], {%1,%2,%3,%4};"
                 :: "r"(dst0), "r"(h[0]), "r"(h[1]), "r"(h[2]), "r"(h[3]));
    asm volatile("st.shared.v4.b32 [%0], {%1,%2,%3,%4};"
                 :: "r"(dst1), "r"(h[4]), "r"(h[5]), "r"(h[6]), "r"(h[7]));
}

template<int NT>
__device__ __forceinline__ void do_mma(uint32_t abase, uint32_t bbase,
                                       float (&c)[2][NT][4], int wm, int wn, int lane)
{
    uint32_t ra = (uint32_t)((wm * 32 + (lane & 15)) * 128 + ((lane >> 4) << 4));
    uint32_t rb = (uint32_t)((wn * (NT * 8) + (lane & 7) + ((lane >> 4) << 3)) * 128
                             + (((lane >> 3) & 1) << 4));
    #pragma unroll
    for (int ks = 0; ks < 4; ++ks) {
        uint32_t a0[4], a1[4];
        ldsm4(a0, abase + sw128(ra + ks * 32));
        ldsm4(a1, abase + sw128(ra + 2048 + ks * 32));
        #pragma unroll
        for (int nt = 0; nt < NT; nt += 2) {
            uint32_t b4[4];
            ldsm4(b4, bbase + sw128(rb + nt * 1024 + ks * 32));
            mma16816(c[0][nt], a0, b4[0], b4[1]);
            mma16816(c[1][nt], a1, b4[0], b4[1]);
            mma16816(c[0][nt + 1], a0, b4[2], b4[3]);
            mma16816(c[1][nt + 1], a1, b4[2], b4[3]);
        }
    }
}

__device__ __forceinline__ void epi(float (&c)[2][4][4], const float* bias,
                                    const float* wop, float* acc2, int wm, int wn, int lane)
{
    float p[2][2][2];
    #pragma unroll
    for (int mt = 0; mt < 2; ++mt)
        #pragma unroll
        for (int h = 0; h < 2; ++h) { p[mt][h][0] = 0.f; p[mt][h][1] = 0.f; }
    #pragma unroll
    for (int mt = 0; mt < 2; ++mt)
    #pragma unroll
    for (int nt = 0; nt < 4; ++nt) {
        int col = wn * 32 + nt * 8 + 2 * (lane & 3);
        float b0 = bias[col], b1v = bias[col + 1];
        float w00 = wop[2 * col], w01 = wop[2 * col + 1];
        float w10 = wop[2 * col + 2], w11 = wop[2 * col + 3];
        float v;
        v = fmaxf(c[mt][nt][0] + b0, 0.f);  p[mt][0][0] += v * w00; p[mt][0][1] += v * w01;
        v = fmaxf(c[mt][nt][1] + b1v, 0.f); p[mt][0][0] += v * w10; p[mt][0][1] += v * w11;
        v = fmaxf(c[mt][nt][2] + b0, 0.f);  p[mt][1][0] += v * w00; p[mt][1][1] += v * w01;
        v = fmaxf(c[mt][nt][3] + b1v, 0.f); p[mt][1][0] += v * w10; p[mt][1][1] += v * w11;
    }
    #pragma unroll
    for (int mt = 0; mt < 2; ++mt)
        #pragma unroll
        for (int h = 0; h < 2; ++h)
            #pragma unroll
            for (int o = 0; o < 2; ++o) {
                p[mt][h][o] += __shfl_xor_sync(0xffffffffu, p[mt][h][o], 1);
                p[mt][h][o] += __shfl_xor_sync(0xffffffffu, p[mt][h][o], 2);
            }
    if ((lane & 3) == 0)
        #pragma unroll
        for (int mt = 0; mt < 2; ++mt)
            #pragma unroll
            for (int h = 0; h < 2; ++h) {
                int row = wm * 32 + mt * 16 + h * 8 + (lane >> 2);
                atomicAdd(&acc2[row * 2 + 0], p[mt][h][0]);
                atomicAdd(&acc2[row * 2 + 1], p[mt][h][1]);
            }
}

__global__ __launch_bounds__(512, 1) void main_kernel(
    const float* __restrict__ b1, const float* __restrict__ b2,
    const float* __restrict__ sb, const float* __restrict__ wo,
    const float* __restrict__ bo, float* __restrict__ out)
{
    extern __shared__ char smc[];
    float* smf = (float*)smc;
    const uint32_t smb = smem_u32(smc);
    const int tid = threadIdx.x, lane = tid & 31, wid = tid >> 5;
    const int wm = wid & 3, wn = wid >> 2;
    const int b = blockIdx.x >> 5, t0 = (blockIdx.x & 31) << 7;

    // B pair0 first (max overlap with rest of prologue)
    {
        uint32_t dst = smb + BT_B + (uint32_t)tid * 16;
        const char* src = (const char*)g_w1h + (size_t)tid * 16;
        #pragma unroll
        for (int r = 0; r < 8; ++r) cp16(dst + r * 8192, src + (size_t)r * 8192);
        CP_COMMIT();
    }
    // XSH from fp16 g_xch via cp.async (159 rows x 8 chunks, stride 144B)
    for (int idx = tid; idx < 159 * 8; idx += 512) {
        int r = idx >> 3, c8 = idx & 7;
        int t = t0 - 31 + r;
        uint32_t d = smb + XSH_B + (uint32_t)(r * 144 + c8 * 16);
        if (t >= 0)
            cp16(d, (const char*)g_xch + (((size_t)b * TT + t) * 64 + c8 * 8) * 2);
        else
            asm volatile("st.shared.v4.b32 [%0], {%1,%1,%1,%1};" :: "r"(d), "r"(0u));
    }
    CP_COMMIT();

    if (tid < 256) smf[tid] = b1[tid];
    if (tid < 128) { smf[256 + tid] = b2[tid]; smf[384 + tid] = sb[tid]; }
    smf[512 + tid] = wo[tid];
    if (tid < 256) smf[1024 + tid] = bo[tid & 1];
    // gate row for this thread's build slot -> registers
    uint32_t gv[8];
    {
        const int m = tid >> 2, kq = (tid & 3) << 4;
        const float* gp = g_a + ((size_t)b * TT + t0 + m) * 64 + kq;
        #pragma unroll
        for (int q = 0; q < 4; ++q) {
            float4 g4 = *(const float4*)(gp + 4 * q);
            asm("cvt.rn.f16x2.f32 %0, %1, %2;" : "=r"(gv[2 * q])     : "f"(g4.y), "f"(g4.x));
            asm("cvt.rn.f16x2.f32 %0, %1, %2;" : "=r"(gv[2 * q + 1]) : "f"(g4.w), "f"(g4.z));
        }
    }
    CP_WAIT(0);
    __syncthreads();   // XSH + B pair0 ready
    build_A(smb, 0, 0, tid, gv);
    build_A(smb, 1, 1, tid, gv);

    // ----- h1 pass: 16 iterations x 2 frames; cp BEFORE mma -----------------
    float c1[2][8][4];
    #pragma unroll
    for (int i = 0; i < 2; ++i)
        #pragma unroll
        for (int j = 0; j < 8; ++j)
            #pragma unroll
            for (int e = 0; e < 4; ++e) c1[i][j][e] = 0.f;

    for (int f = 0; f < 16; ++f) {
        CP_WAIT(0);
        __syncthreads();
        const int s = f & 1;
        if (f < 15) {   // stage NEXT B pair first -> overlaps the mma below
            const int sn = (f + 1) & 1;
            uint32_t dst = smb + BT_B + (uint32_t)(2 * sn) * 32768u + (uint32_t)tid * 16;
            const char* src = (const char*)g_w1h + (size_t)(2 * f + 2) * 32768
                              + (size_t)tid * 16;
            #pragma unroll
            for (int r = 0; r < 8; ++r) cp16(dst + r * 8192, src + (size_t)r * 8192);
            CP_COMMIT();
        }
        do_mma<8>(smb + AT_B + (uint32_t)(2 * s) * 16384u,
                  smb + BT_B + (uint32_t)(2 * s) * 32768u, c1, wm, wn, lane);
        do_mma<8>(smb + AT_B + (uint32_t)(2 * s + 1) * 16384u,
                  smb + BT_B + (uint32_t)(2 * s + 1) * 32768u, c1, wm, wn, lane);
        if (f < 15) {
            const int sn = (f + 1) & 1;
            build_A(smb, 2 * f + 2, 2 * sn, tid, gv);
            build_A(smb, 2 * f + 3, 2 * sn + 1, tid, gv);
        }
    }
    __syncthreads();   // all h1 reads done

    {   // short prologue: SW chunks 0+1 -> BT slot 2 (cp first), A(24),A(25)
        uint32_t dst = smb + BT_B + 2u * 32768u + (uint32_t)tid * 16;
        const char* src = (const char*)g_swh + (size_t)tid * 16;
        #pragma unroll
        for (int r = 0; r < 4; ++r) cp16(dst + r * 8192, src + (size_t)r * 8192);
        CP_COMMIT();
        build_A(smb, 24, 0, tid, gv);
        build_A(smb, 25, 1, tid, gv);
    }

    // h1 epilogue: relu(+bias) -> fp16 H1 (BT slots 0,1)
    #pragma unroll
    for (int mt = 0; mt < 2; ++mt)
    #pragma unroll
    for (int nt = 0; nt < 8; ++nt) {
        int colw = nt * 8 + 2 * (lane & 3);
        int colg = wn * 64 + colw;
        float b0v = smf[colg], b1v = smf[colg + 1];
        int r = wm * 32 + mt * 16 + (lane >> 2);
        uint32_t base = smb + BT_B + wn * 16384;
        float v0 = fmaxf(c1[mt][nt][0] + b0v, 0.f), v1 = fmaxf(c1[mt][nt][1] + b1v, 0.f);
        float v2 = fmaxf(c1[mt][nt][2] + b0v, 0.f), v3 = fmaxf(c1[mt][nt][3] + b1v, 0.f);
        uint32_t p0, p1;
        asm("cvt.rn.f16x2.f32 %0,%1,%2;" : "=r"(p0) : "f"(v1), "f"(v0));
        asm("cvt.rn.f16x2.f32 %0,%1,%2;" : "=r"(p1) : "f"(v3), "f"(v2));
        asm volatile("st.shared.b32 [%0], %1;" :: "r"(base + sw128(r * 128 + colw * 2)), "r"(p0));
        asm volatile("st.shared.b32 [%0], %1;" :: "r"(base + sw128((r + 8) * 128 + colw * 2)), "r"(p1));
    }

    // ----- short pass: 4 iterations x 2 frames; cp BEFORE mma ---------------
    float cs[2][4][4];
    #pragma unroll
    for (int i = 0; i < 2; ++i)
        #pragma unroll
        for (int j = 0; j < 4; ++j)
            #pragma unroll
            for (int e = 0; e < 4; ++e) cs[i][j][e] = 0.f;
    for (int j = 0; j < 4; ++j) {
        CP_WAIT(0);
        __syncthreads();
        const int s = j & 1;
        if (j < 3) {        // next SW pair
            const int sn = (j + 1) & 1;
            uint32_t dst = smb + BT_B + (uint32_t)(2 + sn) * 32768u + (uint32_t)tid * 16;
            const char* src = (const char*)g_swh + (size_t)(2 * j + 2) * 16384
                              + (size_t)tid * 16;
            #pragma unroll
            for (int r = 0; r < 4; ++r) cp16(dst + r * 8192, src + (size_t)r * 8192);
            CP_COMMIT();
        } else {            // last iter: stage W2 chunks 0,1 -> AT slots 0,1
            uint32_t dst = smb + AT_B + (uint32_t)tid * 16;
            const char* src = (const char*)g_w2h + (size_t)tid * 16;
            #pragma unroll
            for (int r = 0; r < 4; ++r) cp16(dst + r * 8192, src + (size_t)r * 8192);
            CP_COMMIT();
        }
        uint32_t bbase = smb + BT_B + (uint32_t)(2 + s) * 32768u;
        do_mma<4>(smb + AT_B + (uint32_t)(2 * s) * 16384u, bbase, cs, wm, wn, lane);
        do_mma<4>(smb + AT_B + (uint32_t)(2 * s + 1) * 16384u, bbase + 16384u,
                  cs, wm, wn, lane);
        if (j < 3) {
            const int sn = (j + 1) & 1;
            build_A(smb, 26 + 2 * j, 2 * sn, tid, gv);
            build_A(smb, 27 + 2 * j, 2 * sn + 1, tid, gv);
        }
    }
    __syncthreads();   // all short reads of AT slots 2,3 done

    {   // stage W2 chunks 2,3 -> AT slots 2,3
        uint32_t dst = smb + AT_B + 2u * 16384u + (uint32_t)tid * 16;
        const char* src = (const char*)g_w2h + 32768 + (size_t)tid * 16;
        #pragma unroll
        for (int r = 0; r < 4; ++r) cp16(dst + r * 8192, src + (size_t)r * 8192);
        CP_COMMIT();
    }
    epi(cs, smf + 384, smf + 512 + 256, smf + 1024, wm, wn, lane);   // short epi
    CP_WAIT(0);
    __syncthreads();

    // ----- h2 pass: A = H1 (BT 0,1 as 4 chunks), B = W2 (AT), 1 sync ---------
    float ch[2][4][4];
    #pragma unroll
    for (int i = 0; i < 2; ++i)
        #pragma unroll
        for (int j = 0; j < 4; ++j)
            #pragma unroll
            for (int e = 0; e < 4; ++e) ch[i][j][e] = 0.f;
    #pragma unroll
    for (int kc = 0; kc < 4; ++kc)
        do_mma<4>(smb + BT_B + (uint32_t)kc * 16384u,
                  smb + AT_B + (uint32_t)kc * 16384u, ch, wm, wn, lane);
    epi(ch, smf + 256, smf + 512, smf + 1024, wm, wn, lane);

    __syncthreads();
    if (tid < 128) {
        float a0 = smf[1024 + tid * 2], a1 = smf[1024 + tid * 2 + 1];
        float2 o;
        o.x = 1.f / (1.f + expf(-a0));
        o.y = 1.f / (1.f + expf(-a1));
        ((float2*)out)[b * TT + t0 + tid] = o;
    }
}

// ---------------------------------------------------------------------------
extern "C" void kernel_launch(void* const* d_in, const int* in_sizes, int n_in,
                              void* d_out, int out_size)
{
    const float* x      = (const float*)d_in[0];
    const float* conv_w = (const float*)d_in[1];
    const float* conv_b = (const float*)d_in[2];
    const float* se_w1  = (const float*)d_in[3];
    const float* se_b1  = (const float*)d_in[4];
    const float* se_w2  = (const float*)d_in[5];
    const float* se_b2  = (const float*)d_in[6];
    const float* w1     = (const float*)d_in[7];
    const float* b1     = (const float*)d_in[8];
    const float* w2     = (const float*)d_in[9];
    const float* b2     = (const float*)d_in[10];
    const float* sw     = (const float*)d_in[11];
    const float* sb     = (const float*)d_in[12];
    const float* wo     = (const float*)d_in[13];
    const float* bo     = (const float*)d_in[14];
    float* out = (float*)d_out;

    const int smem2 = 20624 * 4;
    cudaFuncSetAttribute(se_kernel, cudaFuncAttributeMaxDynamicSharedMemorySize, smem2);
    cudaFuncSetAttribute(main_kernel, cudaFuncAttributeMaxDynamicSharedMemorySize, SMEM_TOT);

    prep_conv_kernel<<<408, 256>>>(x, conv_w, conv_b, w1, w2, sw);
    se_kernel<<<BATCH * 32, 256, smem2>>>(se_w1, se_b1, se_w2, se_b2);
    main_kernel<<<BATCH * 32, 512, SMEM_TOT>>>(b1, b2, sb, wo, bo, out);
}

// round 13
// speedup vs baseline: 1.4116x; 1.4116x over previous
#include <cuda_runtime.h>
#include <cuda_fp16.h>
#include <math.h>
#include <stdint.h>

#define BATCH 8
#define TT 4096
#define NMELS 26
#define CONV_K 5
#define CH 64
#define WF 32

__device__ float g_xc[BATCH * TT * CH];
__device__ float g_a [BATCH * TT * CH];
__device__ uint4 g_xch[262144]; // fp16 copy of g_xc (4MB)
__device__ uint4 g_w1h[65536];  // 32 chunks x 32KB fp16 swizzled [n256][k64]
__device__ uint4 g_swh[8192];   //  8 chunks x 16KB [n128][k64]
__device__ uint4 g_w2h[4096];   //  4 chunks x 16KB [n128][k64]

__device__ __forceinline__ uint32_t smem_u32(const void* p) {
    uint32_t a;
    asm("{ .reg .u64 t; cvta.to.shared.u64 t, %1; cvt.u32.u64 %0, t; }" : "=r"(a) : "l"(p));
    return a;
}
__device__ __forceinline__ uint32_t sw128(uint32_t o) { return o ^ ((o >> 3) & 0x70); }
__device__ __forceinline__ void ldsm4(uint32_t (&r)[4], uint32_t a) {
    asm volatile("ldmatrix.sync.aligned.m8n8.x4.shared.b16 {%0,%1,%2,%3}, [%4];"
                 : "=r"(r[0]), "=r"(r[1]), "=r"(r[2]), "=r"(r[3]) : "r"(a));
}
__device__ __forceinline__ void mma16816(float (&d)[4], const uint32_t (&a)[4],
                                         uint32_t b0, uint32_t b1) {
    asm volatile("mma.sync.aligned.m16n8k16.row.col.f32.f16.f16.f32 "
                 "{%0,%1,%2,%3}, {%4,%5,%6,%7}, {%8,%9}, {%0,%1,%2,%3};"
                 : "+f"(d[0]), "+f"(d[1]), "+f"(d[2]), "+f"(d[3])
                 : "r"(a[0]), "r"(a[1]), "r"(a[2]), "r"(a[3]), "r"(b0), "r"(b1));
}
__device__ __forceinline__ void cp16(uint32_t dst, const void* src) {
    asm volatile("cp.async.cg.shared.global [%0], [%1], 16;" :: "r"(dst), "l"(src));
}
#define CP_COMMIT() asm volatile("cp.async.commit_group;" ::: "memory")
#define CP_WAIT(n)  asm volatile("cp.async.wait_group %0;" :: "n"(n) : "memory")

// ---------------------------------------------------------------------------
// fused conv (blocks [0,512), 64 tokens each — Round-11 shape) +
// prep tiles (blocks [512,664) — coalesced 64k x 64n transpose)
// ---------------------------------------------------------------------------
__global__ __launch_bounds__(256, 2) void prep_conv_kernel(
    const float* __restrict__ x, const float* __restrict__ cw,
    const float* __restrict__ cb, const float* __restrict__ w1,
    const float* __restrict__ w2, const float* __restrict__ swp)
{
    __shared__ __align__(16) float sbuf[10152];
    const int tid = threadIdx.x;

    if (blockIdx.x >= 512) {   // ---- prep tile (coalesced transpose) ----
        const int t = blockIdx.x - 512;
        const float* src; unsigned short* dstbase; int N, n0;
        if (t < 128) {
            int f = t >> 2; n0 = (t & 3) * 64;
            src = w1 + (size_t)f * 64 * 256; N = 256;
            dstbase = (unsigned short*)g_w1h + f * 16384;
        } else if (t < 144) {
            int u = t - 128, j = u >> 1; n0 = (u & 1) * 64;
            src = swp + (size_t)j * 64 * 128; N = 128;
            dstbase = (unsigned short*)g_swh + j * 8192;
        } else {
            int u = t - 144, c = u >> 1; n0 = (u & 1) * 64;
            src = w2 + (size_t)c * 64 * 128; N = 128;
            dstbase = (unsigned short*)g_w2h + c * 8192;
        }
        unsigned short* sh = (unsigned short*)sbuf;
        #pragma unroll
        for (int it = 0; it < 16; ++it) {
            int e = it * 256 + tid, kk = e >> 6, nn = e & 63;
            sh[kk * 64 + nn] = __half_as_ushort(__float2half_rn(src[kk * N + n0 + nn]));
        }
        __syncthreads();
        #pragma unroll
        for (int j2 = 0; j2 < 2; ++j2) {
            int G = tid + 256 * j2, n = G >> 3, grp = G & 7, kk0 = grp * 8;
            uint32_t u[4];
            #pragma unroll
            for (int q = 0; q < 4; ++q) {
                uint32_t lo = sh[(kk0 + 2 * q) * 64 + n];
                uint32_t hi = sh[(kk0 + 2 * q + 1) * 64 + n];
                u[q] = lo | (hi << 16);
            }
            uint32_t off = sw128((uint32_t)((n0 + n) * 128 + kk0 * 2));
            *(uint4*)((char*)dstbase + off) = make_uint4(u[0], u[1], u[2], u[3]);
        }
        return;
    }

    // ---- conv: 64 tokens per block (Round-11 shape) ----
    float* xsh = sbuf;             // 68*26 = 1768
    float* wsh = sbuf + 1768;      // 8320
    float* bsh = sbuf + 10088;     // 64
    const int bb = blockIdx.x;
    const int b = bb >> 6, t0 = (bb & 63) << 6;
    for (int idx = tid; idx < 68 * NMELS; idx += 256) {
        int r = idx / NMELS, m = idx - r * NMELS, t = t0 - 4 + r;
        xsh[idx] = (t >= 0) ? x[(b * TT + t) * NMELS + m] : 0.f;
    }
    for (int idx = tid; idx < CONV_K * NMELS * CH; idx += 256) wsh[idx] = cw[idx];
    if (tid < CH) bsh[tid] = cb[tid];
    __syncthreads();
    const int c = tid & 63, tg = tid >> 6;
    unsigned short* xch = (unsigned short*)g_xch;
    #pragma unroll
    for (int g = 0; g < 4; ++g) {
        float acc[4];
        #pragma unroll
        for (int i = 0; i < 4; ++i) acc[i] = bsh[c];
        #pragma unroll
        for (int k = 0; k < CONV_K; ++k)
            #pragma unroll
            for (int m = 0; m < NMELS; ++m) {
                float w = wsh[(k * NMELS + m) * CH + c];
                int base = (tg * 16 + g * 4 + k) * NMELS + m;
                #pragma unroll
                for (int i = 0; i < 4; ++i) acc[i] = fmaf(xsh[base + i * NMELS], w, acc[i]);
            }
        #pragma unroll
        for (int i = 0; i < 4; ++i) {
            size_t idx = (size_t)(b * TT + t0 + tg * 16 + g * 4 + i) * CH + c;
            float v = fmaxf(acc[i], 0.f);
            g_xc[idx] = v;
            xch[idx] = __half_as_ushort(__float2half_rn(v));
        }
    }
}

// ---------------------------------------------------------------------------
__global__ __launch_bounds__(256) void se_kernel(
    const float* __restrict__ sew1, const float* __restrict__ seb1,
    const float* __restrict__ sew2, const float* __restrict__ seb2)
{
    extern __shared__ float sm2[];
    float* xsh = sm2; float* ssh = sm2 + 10176; float* w1s = sm2 + 18496;
    float* w2s = sm2 + 19520; float* b1s = sm2 + 20544; float* b2s = sm2 + 20560;
    const int b = blockIdx.x >> 5, t0 = (blockIdx.x & 31) << 7, tid = threadIdx.x;
    for (int idx = tid; idx < 159 * CH; idx += 256) {
        int r = idx >> 6, cc = idx & 63, t = t0 - 31 + r;
        xsh[idx] = (t >= 0) ? g_xc[(b * TT + t) * CH + cc] : 0.f;
    }
    for (int idx = tid; idx < 1024; idx += 256) { w1s[idx] = sew1[idx]; w2s[idx] = sew2[idx]; }
    if (tid < 16) b1s[tid] = seb1[tid];
    if (tid < CH) b2s[tid] = seb2[tid];
    __syncthreads();
    {
        const int c = tid & 63, tb = (tid >> 6) * 32;
        float s = 0.f;
        #pragma unroll
        for (int f = 0; f < WF; ++f) s += xsh[(tb + f) * CH + c];
        ssh[tb * 65 + c] = s * 0.03125f;
        for (int i = 1; i < 32; ++i) {
            s += xsh[(tb + i + 31) * CH + c] - xsh[(tb + i - 1) * CH + c];
            ssh[(tb + i) * 65 + c] = s * 0.03125f;
        }
    }
    __syncthreads();
    if (tid < 128) {
        float hid[16];
        #pragma unroll
        for (int j = 0; j < 16; ++j) hid[j] = b1s[j];
        for (int cc = 0; cc < CH; ++cc) {
            float sv = ssh[tid * 65 + cc];
            #pragma unroll
            for (int j = 0; j < 16; ++j) hid[j] = fmaf(sv, w1s[cc * 16 + j], hid[j]);
        }
        #pragma unroll
        for (int j = 0; j < 16; ++j) hid[j] = fmaxf(hid[j], 0.f);
        for (int cc = 0; cc < CH; ++cc) {
            float v = b2s[cc];
            #pragma unroll
            for (int j = 0; j < 16; ++j) v = fmaf(hid[j], w2s[j * CH + cc], v);
            g_a[(b * TT + t0 + tid) * CH + cc] = 1.f / (1.f + expf(-v));
        }
    }
}

// ---------------------------------------------------------------------------
// main kernel: unchanged from the 172.8us version (Round 11).
// ---------------------------------------------------------------------------
#define XSH_B 5120
#define AT_B  28160
#define BT_B  93696
#define SMEM_TOT 224768

__device__ __forceinline__ void build_A(uint32_t smb, int f, int slot, int tid,
                                        const uint32_t (&gv)[8])
{
    const int m = tid >> 2, kq = (tid & 3) << 4;
    uint32_t xaddr = smb + XSH_B + (uint32_t)(((m + f) * 72 + kq) * 2);
    uint32_t o = (uint32_t)(m * 128 + kq * 2);
    uint32_t abase = smb + AT_B + (uint32_t)slot * 16384u;
    uint32_t dst0 = abase + sw128(o);
    uint32_t dst1 = abase + sw128(o + 16);
    uint32_t xv[8], h[8];
    asm("ld.shared.v4.b32 {%0,%1,%2,%3}, [%4];"
        : "=r"(xv[0]), "=r"(xv[1]), "=r"(xv[2]), "=r"(xv[3]) : "r"(xaddr));
    asm("ld.shared.v4.b32 {%0,%1,%2,%3}, [%4];"
        : "=r"(xv[4]), "=r"(xv[5]), "=r"(xv[6]), "=r"(xv[7]) : "r"(xaddr + 16));
    #pragma unroll
    for (int i = 0; i < 8; ++i)
        asm("mul.rn.f16x2 %0, %1, %2;" : "=r"(h[i]) : "r"(xv[i]), "r"(gv[i]));
    asm volatile("st.shared.v4.b32 [%0], {%1,%2,%3,%4};"
                 :: "r"(dst0), "r"(h[0]), "r"(h[1]), "r"(h[2]), "r"(h[3]));
    asm volatile("st.shared.v4.b32 [%0], {%1,%2,%3,%4};"
                 :: "r"(dst1), "r"(h[4]), "r"(h[5]), "r"(h[6]), "r"(h[7]));
}

template<int NT>
__device__ __forceinline__ void do_mma(uint32_t abase, uint32_t bbase,
                                       float (&c)[2][NT][4], int wm, int wn, int lane)
{
    uint32_t ra = (uint32_t)((wm * 32 + (lane & 15)) * 128 + ((lane >> 4) << 4));
    uint32_t rb = (uint32_t)((wn * (NT * 8) + (lane & 7) + ((lane >> 4) << 3)) * 128
                             + (((lane >> 3) & 1) << 4));
    #pragma unroll
    for (int ks = 0; ks < 4; ++ks) {
        uint32_t a0[4], a1[4];
        ldsm4(a0, abase + sw128(ra + ks * 32));
        ldsm4(a1, abase + sw128(ra + 2048 + ks * 32));
        #pragma unroll
        for (int nt = 0; nt < NT; nt += 2) {
            uint32_t b4[4];
            ldsm4(b4, bbase + sw128(rb + nt * 1024 + ks * 32));
            mma16816(c[0][nt], a0, b4[0], b4[1]);
            mma16816(c[1][nt], a1, b4[0], b4[1]);
            mma16816(c[0][nt + 1], a0, b4[2], b4[3]);
            mma16816(c[1][nt + 1], a1, b4[2], b4[3]);
        }
    }
}

__device__ __forceinline__ void epi(float (&c)[2][4][4], const float* bias,
                                    const float* wop, float* acc2, int wm, int wn, int lane)
{
    float p[2][2][2];
    #pragma unroll
    for (int mt = 0; mt < 2; ++mt)
        #pragma unroll
        for (int h = 0; h < 2; ++h) { p[mt][h][0] = 0.f; p[mt][h][1] = 0.f; }
    #pragma unroll
    for (int mt = 0; mt < 2; ++mt)
    #pragma unroll
    for (int nt = 0; nt < 4; ++nt) {
        int col = wn * 32 + nt * 8 + 2 * (lane & 3);
        float b0 = bias[col], b1v = bias[col + 1];
        float w00 = wop[2 * col], w01 = wop[2 * col + 1];
        float w10 = wop[2 * col + 2], w11 = wop[2 * col + 3];
        float v;
        v = fmaxf(c[mt][nt][0] + b0, 0.f);  p[mt][0][0] += v * w00; p[mt][0][1] += v * w01;
        v = fmaxf(c[mt][nt][1] + b1v, 0.f); p[mt][0][0] += v * w10; p[mt][0][1] += v * w11;
        v = fmaxf(c[mt][nt][2] + b0, 0.f);  p[mt][1][0] += v * w00; p[mt][1][1] += v * w01;
        v = fmaxf(c[mt][nt][3] + b1v, 0.f); p[mt][1][0] += v * w10; p[mt][1][1] += v * w11;
    }
    #pragma unroll
    for (int mt = 0; mt < 2; ++mt)
        #pragma unroll
        for (int h = 0; h < 2; ++h)
            #pragma unroll
            for (int o = 0; o < 2; ++o) {
                p[mt][h][o] += __shfl_xor_sync(0xffffffffu, p[mt][h][o], 1);
                p[mt][h][o] += __shfl_xor_sync(0xffffffffu, p[mt][h][o], 2);
            }
    if ((lane & 3) == 0)
        #pragma unroll
        for (int mt = 0; mt < 2; ++mt)
            #pragma unroll
            for (int h = 0; h < 2; ++h) {
                int row = wm * 32 + mt * 16 + h * 8 + (lane >> 2);
                atomicAdd(&acc2[row * 2 + 0], p[mt][h][0]);
                atomicAdd(&acc2[row * 2 + 1], p[mt][h][1]);
            }
}

__global__ __launch_bounds__(512, 1) void main_kernel(
    const float* __restrict__ b1, const float* __restrict__ b2,
    const float* __restrict__ sb, const float* __restrict__ wo,
    const float* __restrict__ bo, float* __restrict__ out)
{
    extern __shared__ char smc[];
    float* smf = (float*)smc;
    const uint32_t smb = smem_u32(smc);
    const int tid = threadIdx.x, lane = tid & 31, wid = tid >> 5;
    const int wm = wid & 3, wn = wid >> 2;
    const int b = blockIdx.x >> 5, t0 = (blockIdx.x & 31) << 7;

    // B pair0 first (max overlap with rest of prologue)
    {
        uint32_t dst = smb + BT_B + (uint32_t)tid * 16;
        const char* src = (const char*)g_w1h + (size_t)tid * 16;
        #pragma unroll
        for (int r = 0; r < 8; ++r) cp16(dst + r * 8192, src + (size_t)r * 8192);
        CP_COMMIT();
    }
    // XSH from fp16 g_xch via cp.async (159 rows x 8 chunks, stride 144B)
    for (int idx = tid; idx < 159 * 8; idx += 512) {
        int r = idx >> 3, c8 = idx & 7;
        int t = t0 - 31 + r;
        uint32_t d = smb + XSH_B + (uint32_t)(r * 144 + c8 * 16);
        if (t >= 0)
            cp16(d, (const char*)g_xch + (((size_t)b * TT + t) * 64 + c8 * 8) * 2);
        else
            asm volatile("st.shared.v4.b32 [%0], {%1,%1,%1,%1};" :: "r"(d), "r"(0u));
    }
    CP_COMMIT();

    if (tid < 256) smf[tid] = b1[tid];
    if (tid < 128) { smf[256 + tid] = b2[tid]; smf[384 + tid] = sb[tid]; }
    smf[512 + tid] = wo[tid];
    if (tid < 256) smf[1024 + tid] = bo[tid & 1];
    // gate row for this thread's build slot -> registers
    uint32_t gv[8];
    {
        const int m = tid >> 2, kq = (tid & 3) << 4;
        const float* gp = g_a + ((size_t)b * TT + t0 + m) * 64 + kq;
        #pragma unroll
        for (int q = 0; q < 4; ++q) {
            float4 g4 = *(const float4*)(gp + 4 * q);
            asm("cvt.rn.f16x2.f32 %0, %1, %2;" : "=r"(gv[2 * q])     : "f"(g4.y), "f"(g4.x));
            asm("cvt.rn.f16x2.f32 %0, %1, %2;" : "=r"(gv[2 * q + 1]) : "f"(g4.w), "f"(g4.z));
        }
    }
    CP_WAIT(0);
    __syncthreads();   // XSH + B pair0 ready
    build_A(smb, 0, 0, tid, gv);
    build_A(smb, 1, 1, tid, gv);

    // ----- h1 pass: 16 iterations x 2 frames; cp BEFORE mma -----------------
    float c1[2][8][4];
    #pragma unroll
    for (int i = 0; i < 2; ++i)
        #pragma unroll
        for (int j = 0; j < 8; ++j)
            #pragma unroll
            for (int e = 0; e < 4; ++e) c1[i][j][e] = 0.f;

    for (int f = 0; f < 16; ++f) {
        CP_WAIT(0);
        __syncthreads();
        const int s = f & 1;
        if (f < 15) {   // stage NEXT B pair first -> overlaps the mma below
            const int sn = (f + 1) & 1;
            uint32_t dst = smb + BT_B + (uint32_t)(2 * sn) * 32768u + (uint32_t)tid * 16;
            const char* src = (const char*)g_w1h + (size_t)(2 * f + 2) * 32768
                              + (size_t)tid * 16;
            #pragma unroll
            for (int r = 0; r < 8; ++r) cp16(dst + r * 8192, src + (size_t)r * 8192);
            CP_COMMIT();
        }
        do_mma<8>(smb + AT_B + (uint32_t)(2 * s) * 16384u,
                  smb + BT_B + (uint32_t)(2 * s) * 32768u, c1, wm, wn, lane);
        do_mma<8>(smb + AT_B + (uint32_t)(2 * s + 1) * 16384u,
                  smb + BT_B + (uint32_t)(2 * s + 1) * 32768u, c1, wm, wn, lane);
        if (f < 15) {
            const int sn = (f + 1) & 1;
            build_A(smb, 2 * f + 2, 2 * sn, tid, gv);
            build_A(smb, 2 * f + 3, 2 * sn + 1, tid, gv);
        }
    }
    __syncthreads();   // all h1 reads done

    {   // short prologue: SW chunks 0+1 -> BT slot 2 (cp first), A(24),A(25)
        uint32_t dst = smb + BT_B + 2u * 32768u + (uint32_t)tid * 16;
        const char* src = (const char*)g_swh + (size_t)tid * 16;
        #pragma unroll
        for (int r = 0; r < 4; ++r) cp16(dst + r * 8192, src + (size_t)r * 8192);
        CP_COMMIT();
        build_A(smb, 24, 0, tid, gv);
        build_A(smb, 25, 1, tid, gv);
    }

    // h1 epilogue: relu(+bias) -> fp16 H1 (BT slots 0,1)
    #pragma unroll
    for (int mt = 0; mt < 2; ++mt)
    #pragma unroll
    for (int nt = 0; nt < 8; ++nt) {
        int colw = nt * 8 + 2 * (lane & 3);
        int colg = wn * 64 + colw;
        float b0v = smf[colg], b1v = smf[colg + 1];
        int r = wm * 32 + mt * 16 + (lane >> 2);
        uint32_t base = smb + BT_B + wn * 16384;
        float v0 = fmaxf(c1[mt][nt][0] + b0v, 0.f), v1 = fmaxf(c1[mt][nt][1] + b1v, 0.f);
        float v2 = fmaxf(c1[mt][nt][2] + b0v, 0.f), v3 = fmaxf(c1[mt][nt][3] + b1v, 0.f);
        uint32_t p0, p1;
        asm("cvt.rn.f16x2.f32 %0,%1,%2;" : "=r"(p0) : "f"(v1), "f"(v0));
        asm("cvt.rn.f16x2.f32 %0,%1,%2;" : "=r"(p1) : "f"(v3), "f"(v2));
        asm volatile("st.shared.b32 [%0], %1;" :: "r"(base + sw128(r * 128 + colw * 2)), "r"(p0));
        asm volatile("st.shared.b32 [%0], %1;" :: "r"(base + sw128((r + 8) * 128 + colw * 2)), "r"(p1));
    }

    // ----- short pass: 4 iterations x 2 frames; cp BEFORE mma ---------------
    float cs[2][4][4];
    #pragma unroll
    for (int i = 0; i < 2; ++i)
        #pragma unroll
        for (int j = 0; j < 4; ++j)
            #pragma unroll
            for (int e = 0; e < 4; ++e) cs[i][j][e] = 0.f;
    for (int j = 0; j < 4; ++j) {
        CP_WAIT(0);
        __syncthreads();
        const int s = j & 1;
        if (j < 3) {        // next SW pair
            const int sn = (j + 1) & 1;
            uint32_t dst = smb + BT_B + (uint32_t)(2 + sn) * 32768u + (uint32_t)tid * 16;
            const char* src = (const char*)g_swh + (size_t)(2 * j + 2) * 16384
                              + (size_t)tid * 16;
            #pragma unroll
            for (int r = 0; r < 4; ++r) cp16(dst + r * 8192, src + (size_t)r * 8192);
            CP_COMMIT();
        } else {            // last iter: stage W2 chunks 0,1 -> AT slots 0,1
            uint32_t dst = smb + AT_B + (uint32_t)tid * 16;
            const char* src = (const char*)g_w2h + (size_t)tid * 16;
            #pragma unroll
            for (int r = 0; r < 4; ++r) cp16(dst + r * 8192, src + (size_t)r * 8192);
            CP_COMMIT();
        }
        uint32_t bbase = smb + BT_B + (uint32_t)(2 + s) * 32768u;
        do_mma<4>(smb + AT_B + (uint32_t)(2 * s) * 16384u, bbase, cs, wm, wn, lane);
        do_mma<4>(smb + AT_B + (uint32_t)(2 * s + 1) * 16384u, bbase + 16384u,
                  cs, wm, wn, lane);
        if (j < 3) {
            const int sn = (j + 1) & 1;
            build_A(smb, 26 + 2 * j, 2 * sn, tid, gv);
            build_A(smb, 27 + 2 * j, 2 * sn + 1, tid, gv);
        }
    }
    __syncthreads();   // all short reads of AT slots 2,3 done

    {   // stage W2 chunks 2,3 -> AT slots 2,3
        uint32_t dst = smb + AT_B + 2u * 16384u + (uint32_t)tid * 16;
        const char* src = (const char*)g_w2h + 32768 + (size_t)tid * 16;
        #pragma unroll
        for (int r = 0; r < 4; ++r) cp16(dst + r * 8192, src + (size_t)r * 8192);
        CP_COMMIT();
    }
    epi(cs, smf + 384, smf + 512 + 256, smf + 1024, wm, wn, lane);   // short epi
    CP_WAIT(0);
    __syncthreads();

    // ----- h2 pass: A = H1 (BT 0,1 as 4 chunks), B = W2 (AT), 1 sync ---------
    float ch[2][4][4];
    #pragma unroll
    for (int i = 0; i < 2; ++i)
        #pragma unroll
        for (int j = 0; j < 4; ++j)
            #pragma unroll
            for (int e = 0; e < 4; ++e) ch[i][j][e] = 0.f;
    #pragma unroll
    for (int kc = 0; kc < 4; ++kc)
        do_mma<4>(smb + BT_B + (uint32_t)kc * 16384u,
                  smb + AT_B + (uint32_t)kc * 16384u, ch, wm, wn, lane);
    epi(ch, smf + 256, smf + 512, smf + 1024, wm, wn, lane);

    __syncthreads();
    if (tid < 128) {
        float a0 = smf[1024 + tid * 2], a1 = smf[1024 + tid * 2 + 1];
        float2 o;
        o.x = 1.f / (1.f + expf(-a0));
        o.y = 1.f / (1.f + expf(-a1));
        ((float2*)out)[b * TT + t0 + tid] = o;
    }
}

// ---------------------------------------------------------------------------
extern "C" void kernel_launch(void* const* d_in, const int* in_sizes, int n_in,
                              void* d_out, int out_size)
{
    const float* x      = (const float*)d_in[0];
    const float* conv_w = (const float*)d_in[1];
    const float* conv_b = (const float*)d_in[2];
    const float* se_w1  = (const float*)d_in[3];
    const float* se_b1  = (const float*)d_in[4];
    const float* se_w2  = (const float*)d_in[5];
    const float* se_b2  = (const float*)d_in[6];
    const float* w1     = (const float*)d_in[7];
    const float* b1     = (const float*)d_in[8];
    const float* w2     = (const float*)d_in[9];
    const float* b2     = (const float*)d_in[10];
    const float* sw     = (const float*)d_in[11];
    const float* sb     = (const float*)d_in[12];
    const float* wo     = (const float*)d_in[13];
    const float* bo     = (const float*)d_in[14];
    float* out = (float*)d_out;

    const int smem2 = 20624 * 4;
    cudaFuncSetAttribute(se_kernel, cudaFuncAttributeMaxDynamicSharedMemorySize, smem2);
    cudaFuncSetAttribute(main_kernel, cudaFuncAttributeMaxDynamicSharedMemorySize, SMEM_TOT);

    prep_conv_kernel<<<664, 256>>>(x, conv_w, conv_b, w1, w2, sw);
    se_kernel<<<BATCH * 32, 256, smem2>>>(se_w1, se_b1, se_w2, se_b2);
    main_kernel<<<BATCH * 32, 512, SMEM_TOT>>>(b1, b2, sb, wo, bo, out);
}